// round 14
// baseline (speedup 1.0000x reference)
#include <cuda_runtime.h>
#include <math.h>

// ---------------- problem constants ----------------
#define BSZ    16
#define BOTC   26
#define NTOK   50625          // 15^4
#define NLAYER 6
#define LN_EPS 1e-5f
#define ATT_SCALE 0.5f        // DH^-0.5

#define TPB_B  256
#define TPT_B  4
#define NBLK_B 50             // ceil(50625 / (256*4))
#define TPB_C  128
#define NBLK_C ((NTOK + TPB_C - 1) / TPB_C)   // 396
#define TPB_E  256
#define NBLK_E ((NTOK + TPB_E - 1) / TPB_E)   // 198
#define QSTRIDE NBLK_C        // >= NBLK_E

// ---------------- device scratch (static, allowed) ----------------
__device__ float  g_x[(size_t)BSZ * NTOK * 16];          // activations (~52MB, L2-resident)
__device__ float4 g_cos[NTOK];
__device__ float4 g_sin[NTOK];
__device__ float  g_qpart[(size_t)BSZ * 40 * QSTRIDE];   // [b][slot=h*5+c][blk]
__device__ float  g_kpart[(size_t)BSZ * 40 * NBLK_B];
__device__ float  g_gq[BSZ * 32];
__device__ float  g_gk[BSZ * 32];
__device__ unsigned g_cntQ[BSZ];
__device__ unsigned g_cntK[BSZ];

// ---------------- f32x2 packed-FMA helpers ----------------
static __device__ __forceinline__ unsigned long long f2pack(float lo, float hi) {
    unsigned long long r;
    asm("mov.b64 %0, {%1, %2};" : "=l"(r) : "f"(lo), "f"(hi));
    return r;
}
static __device__ __forceinline__ void f2unpack(unsigned long long v, float& lo, float& hi) {
    asm("mov.b64 {%0, %1}, %2;" : "=f"(lo), "=f"(hi) : "l"(v));
}
static __device__ __forceinline__ unsigned long long f2fma(unsigned long long a,
                                                           unsigned long long b,
                                                           unsigned long long c) {
    unsigned long long d;
    asm("fma.rn.f32x2 %0, %1, %2, %3;" : "=l"(d) : "l"(a), "l"(b), "l"(c));
    return d;
}

static __device__ __forceinline__ float warp_sum(float v) {
#pragma unroll
    for (int off = 16; off > 0; off >>= 1)
        v += __shfl_down_sync(0xffffffffu, v, off);
    return v;
}

// layernorm over 16, emit packed (y_d, y_d) per dim
static __device__ __forceinline__ void ln_pack16(const float* xv, const float* g, const float* b,
                                                 unsigned long long* y2) {
    float mu = 0.f;
#pragma unroll
    for (int d = 0; d < 16; d++) mu += xv[d];
    mu *= (1.f / 16.f);
    float var = 0.f;
#pragma unroll
    for (int d = 0; d < 16; d++) { float t = xv[d] - mu; var += t * t; }
    var *= (1.f / 16.f);
    float r = rsqrtf(var + LN_EPS);
#pragma unroll
    for (int d = 0; d < 16; d++) {
        float y = (xv[d] - mu) * r * g[d] + b[d];
        y2[d] = f2pack(y, y);
    }
}

// block-reduce (s,v) partials -> global partial slot; last block per batch
// combines all partials and writes normalized 32-vector to gout.
template <int NW, int STRIDE>
static __device__ __forceinline__ void reduce_and_combine(
    float s[8], float v[8][4],
    float* __restrict__ gpart, unsigned* __restrict__ cnt,
    float* __restrict__ gout, int b)
{
    __shared__ float sred[NW][40];
    __shared__ float sfin[40];
    __shared__ int lastFlag;
    const int tid = threadIdx.x, lane = tid & 31, warp = tid >> 5;

#pragma unroll
    for (int h = 0; h < 8; h++) {
        s[h] = warp_sum(s[h]);
#pragma unroll
        for (int j = 0; j < 4; j++) v[h][j] = warp_sum(v[h][j]);
    }
    if (lane == 0) {
#pragma unroll
        for (int h = 0; h < 8; h++) {
            sred[warp][h * 5 + 0] = s[h];
            sred[warp][h * 5 + 1] = v[h][0];
            sred[warp][h * 5 + 2] = v[h][1];
            sred[warp][h * 5 + 3] = v[h][2];
            sred[warp][h * 5 + 4] = v[h][3];
        }
    }
    __syncthreads();
    if (tid < 40) {
        float a = 0.f;
#pragma unroll
        for (int w = 0; w < NW; w++) a += sred[w][tid];
        gpart[((size_t)b * 40 + tid) * STRIDE + blockIdx.x] = a;
        __threadfence();
    }
    __syncthreads();
    if (tid == 0)
        lastFlag = (atomicInc(&cnt[b], gridDim.x - 1) == gridDim.x - 1);
    __syncthreads();
    if (lastFlag) {
        const int nblk = gridDim.x;
        for (int slot = warp; slot < 40; slot += NW) {
            const float* p = gpart + ((size_t)b * 40 + slot) * STRIDE;
            float a = 0.f;
            for (int i = lane; i < nblk; i += 32) a += p[i];
            a = warp_sum(a);
            if (lane == 0) sfin[slot] = a;
        }
        __syncthreads();
        if (tid < 32) {
            int h = tid >> 2, j = tid & 3;
            gout[b * 32 + tid] = sfin[h * 5 + 1 + j] / sfin[h * 5];
        }
    }
}

// ---------------- rotary tables ----------------
__global__ void k_rotary() {
    int n = blockIdx.x * blockDim.x + threadIdx.x;
    if (n >= NTOK) return;
    float fn = (float)n;
    float a0 = fn * 3.14159265358979323846f;   // fp32(pi), matches reference rounding
    float a1 = fn * 15.70796326794896619231f;  // fp32(5*pi)
    float s0, c0, s1, c1;
    sincosf(a0, &s0, &c0);
    sincosf(a1, &s1, &c1);
    g_cos[n] = make_float4(c0, c0, c1, c1);
    g_sin[n] = make_float4(s0, s0, s1, s1);
}

// ---------------- embedding + layer-0 q-softmax partials ----------------
__global__ void __launch_bounds__(TPB_E) k_embed(const float* __restrict__ corr,
                                                 const float* __restrict__ W_emb,
                                                 const float* __restrict__ b_emb,
                                                 const float* __restrict__ lng,
                                                 const float* __restrict__ lnb,
                                                 const float* __restrict__ Wqkv,
                                                 const float* __restrict__ wql) {
    __shared__ __align__(16) float sW[BOTC * 16];
    __shared__ __align__(16) float sWq[512];
    __shared__ float sb[16], sg[16], sb1[16], swl[4];
    const int tid = threadIdx.x;
    const int b = blockIdx.y;
    for (int t = tid; t < BOTC * 16; t += TPB_E) sW[t] = W_emb[t];
    for (int t = tid; t < 512; t += TPB_E) sWq[t] = Wqkv[(t >> 5) * 96 + (t & 31)];
    if (tid < 16) { sb[tid] = b_emb[tid]; sg[tid] = lng[tid]; sb1[tid] = lnb[tid]; }
    if (tid < 4) swl[tid] = wql[tid];
    __syncthreads();

    float s[8], v[8][4];
#pragma unroll
    for (int h = 0; h < 8; h++) { s[h] = 0.f; v[h][0] = v[h][1] = v[h][2] = v[h][3] = 0.f; }

    int n = blockIdx.x * TPB_E + tid;
    if (n < NTOK) {
        const unsigned long long* w2 = (const unsigned long long*)sW;
        unsigned long long acc[8];
#pragma unroll
        for (int e = 0; e < 8; e++) acc[e] = f2pack(sb[2 * e], sb[2 * e + 1]);
        const float* cp = corr + (size_t)b * BOTC * NTOK + n;
#pragma unroll
        for (int c = 0; c < BOTC; c++) {
            float rc = fmaxf(cp[(size_t)c * NTOK], 0.f);
            unsigned long long r2 = f2pack(rc, rc);
#pragma unroll
            for (int e = 0; e < 8; e++) acc[e] = f2fma(r2, w2[c * 8 + e], acc[e]);
        }
        float xv[16];
        float* xp = g_x + ((size_t)b * NTOK + n) * 16;
#pragma unroll
        for (int e = 0; e < 8; e++) {
            float lo, hi; f2unpack(acc[e], lo, hi);
            xv[2 * e] = lo; xv[2 * e + 1] = hi;
            *(float2*)(xp + 2 * e) = make_float2(lo, hi);
        }
        // layer-0 q partials
        unsigned long long y2[16];
        ln_pack16(xv, sg, sb1, y2);
        float4 cv = g_cos[n], sv = g_sin[n];
        const ulonglong2* wq4 = (const ulonglong2*)sWq;
#pragma unroll
        for (int h = 0; h < 8; h++) {
            unsigned long long p0 = 0ull, p1 = 0ull;
#pragma unroll
            for (int d = 0; d < 16; d++) {
                ulonglong2 w = wq4[d * 8 + h];
                p0 = f2fma(y2[d], w.x, p0);
                p1 = f2fma(y2[d], w.y, p1);
            }
            float t0, t1, t2, t3;
            f2unpack(p0, t0, t1); f2unpack(p1, t2, t3);
            float lg = (t0 * swl[0] + t1 * swl[1] + t2 * swl[2] + t3 * swl[3]) * ATT_SCALE;
            float e = __expf(lg);
            float a0 = t0 * cv.x - t1 * sv.x;
            float a1 = t1 * cv.y + t0 * sv.y;
            float a2 = t2 * cv.z - t3 * sv.z;
            float a3 = t3 * cv.w + t2 * sv.w;
            s[h] += e;
            v[h][0] += e * a0; v[h][1] += e * a1; v[h][2] += e * a2; v[h][3] += e * a3;
        }
    }
    reduce_and_combine<TPB_E / 32, QSTRIDE>(s, v, g_qpart, g_cntQ, g_gq, b);
}

// ---------------- pass B: k-softmax sweep (+ fused g_gk combine) ----------------
__global__ void __launch_bounds__(TPB_B) k_passB(const float* __restrict__ lng,
                                                 const float* __restrict__ lnb,
                                                 const float* __restrict__ Wqkv,
                                                 const float* __restrict__ wkl) {
    __shared__ __align__(16) float sW[512];
    __shared__ float sg[16], sb[16], swl[2], sgq[32];
    const int tid = threadIdx.x;
    const int b = blockIdx.y;
    for (int t = tid; t < 512; t += TPB_B) sW[t] = Wqkv[(t >> 5) * 96 + 32 + (t & 31)];
    if (tid < 16) { sg[tid] = lng[tid]; sb[tid] = lnb[tid]; }
    if (tid < 2)  swl[tid] = wkl[tid];
    if (tid < 32) sgq[tid] = g_gq[b * 32 + tid];
    __syncthreads();

    float s[8], v[8][4];
#pragma unroll
    for (int h = 0; h < 8; h++) { s[h] = 0.f; v[h][0] = v[h][1] = v[h][2] = v[h][3] = 0.f; }

    const ulonglong2* w4 = (const ulonglong2*)sW;

#pragma unroll
    for (int t = 0; t < TPT_B; t++) {
        int n = blockIdx.x * (TPB_B * TPT_B) + t * TPB_B + tid;
        if (n < NTOK) {
            const float* xp = g_x + ((size_t)b * NTOK + n) * 16;
            float xv[16];
#pragma unroll
            for (int i = 0; i < 4; i++) {
                float4 xl = ((const float4*)xp)[i];
                xv[4 * i] = xl.x; xv[4 * i + 1] = xl.y; xv[4 * i + 2] = xl.z; xv[4 * i + 3] = xl.w;
            }
            unsigned long long y2[16];
            ln_pack16(xv, sg, sb, y2);
            float4 cv = g_cos[n], sv = g_sin[n];
#pragma unroll
            for (int h = 0; h < 8; h++) {
                unsigned long long p0 = 0ull, p1 = 0ull;
#pragma unroll
                for (int d = 0; d < 16; d++) {
                    ulonglong2 w = w4[d * 8 + h];
                    p0 = f2fma(y2[d], w.x, p0);
                    p1 = f2fma(y2[d], w.y, p1);
                }
                float t0, t1, t2, t3;
                f2unpack(p0, t0, t1); f2unpack(p1, t2, t3);
                float k20 = t0 * sgq[h * 4 + 0] + t1 * sgq[h * 4 + 1];
                float k21 = t2 * sgq[h * 4 + 2] + t3 * sgq[h * 4 + 3];
                float lg = (k20 * swl[0] + k21 * swl[1]) * ATT_SCALE;
                float e = __expf(lg);
                float a0 = t0 * cv.x - t1 * sv.x;
                float a1 = t1 * cv.y + t0 * sv.y;
                float a2 = t2 * cv.z - t3 * sv.z;
                float a3 = t3 * cv.w + t2 * sv.w;
                s[h] += e;
                v[h][0] += e * a0; v[h][1] += e * a1; v[h][2] += e * a2; v[h][3] += e * a3;
            }
        }
    }
    reduce_and_combine<TPB_B / 32, NBLK_B>(s, v, g_kpart, g_cntK, g_gk, b);
}

// ---------------- pass C: attention out + FFN; fused next-layer q partials or final out ----------------
template <bool DO_Q>
__global__ void __launch_bounds__(TPB_C) k_passC(
    const float* __restrict__ lng1, const float* __restrict__ lnb1,
    const float* __restrict__ Wqkv,
    const float* __restrict__ Wr, const float* __restrict__ br,
    const float* __restrict__ Wo, const float* __restrict__ bo,
    const float* __restrict__ lng2, const float* __restrict__ lnb2,
    const float* __restrict__ Wf1, const float* __restrict__ bf1,
    const float* __restrict__ Wf2, const float* __restrict__ bf2,
    const float* __restrict__ lng1n, const float* __restrict__ lnb1n,
    const float* __restrict__ Wqkvn, const float* __restrict__ wqln,
    const float* __restrict__ Wout, const float* __restrict__ bout,
    float* __restrict__ out)
{
    __shared__ __align__(16) float sWq[512];
    __shared__ __align__(16) float sWv[512];
    __shared__ __align__(16) float sWo[512];
    __shared__ __align__(16) float sW1[1024];
    __shared__ __align__(16) float sW2[1024];
    __shared__ __align__(16) float sWqn[512];
    __shared__ float sg1[16], sb1[16], sg2[16], sb2[16], sgn[16], sbn[16];
    __shared__ float sWr[8], sbr[4], sbo[16], sbf1[64], sbf2[16], sgk[32], swln[4], sWout[16];
    const int tid = threadIdx.x;
    const int b = blockIdx.y;
    for (int t = tid; t < 512; t += TPB_C) {
        sWq[t] = Wqkv[(t >> 5) * 96 + (t & 31)];
        sWv[t] = Wqkv[(t >> 5) * 96 + 64 + (t & 31)];
        sWo[t] = Wo[t];
        if (DO_Q) sWqn[t] = Wqkvn[(t >> 5) * 96 + (t & 31)];
    }
    for (int t = tid; t < 1024; t += TPB_C) { sW1[t] = Wf1[t]; sW2[t] = Wf2[t]; }
    if (tid < 16) {
        sg1[tid] = lng1[tid]; sb1[tid] = lnb1[tid];
        sg2[tid] = lng2[tid]; sb2[tid] = lnb2[tid];
        sbo[tid] = bo[tid];   sbf2[tid] = bf2[tid];
        if (DO_Q) { sgn[tid] = lng1n[tid]; sbn[tid] = lnb1n[tid]; }
        else      { sWout[tid] = Wout[tid]; }
    }
    if (tid < 8) sWr[tid] = Wr[tid];
    if (tid < 4) { sbr[tid] = br[tid]; if (DO_Q) swln[tid] = wqln[tid]; }
    if (tid < 64) sbf1[tid] = bf1[tid];
    if (tid < 32) sgk[tid] = g_gk[b * 32 + tid];
    __syncthreads();

    const int n = blockIdx.x * TPB_C + tid;
    const bool act = (n < NTOK);

    float s[8], v[8][4];
    if (DO_Q) {
#pragma unroll
        for (int h = 0; h < 8; h++) { s[h] = 0.f; v[h][0] = v[h][1] = v[h][2] = v[h][3] = 0.f; }
    }

    if (act) {
        float* xp = g_x + ((size_t)b * NTOK + n) * 16;
        float xv[16];
#pragma unroll
        for (int i = 0; i < 4; i++) {
            float4 xl = ((const float4*)xp)[i];
            xv[4 * i] = xl.x; xv[4 * i + 1] = xl.y; xv[4 * i + 2] = xl.z; xv[4 * i + 3] = xl.w;
        }

        unsigned long long y2[16];
        ln_pack16(xv, sg1, sb1, y2);

        unsigned long long oacc[8];
#pragma unroll
        for (int e = 0; e < 8; e++) oacc[e] = f2pack(sbo[2 * e], sbo[2 * e + 1]);

        const ulonglong2* wq4 = (const ulonglong2*)sWq;
        const ulonglong2* wv4 = (const ulonglong2*)sWv;
        const unsigned long long* wo2 = (const unsigned long long*)sWo;

#pragma unroll
        for (int h = 0; h < 8; h++) {
            unsigned long long qa0 = 0ull, qa1 = 0ull, va0 = 0ull, va1 = 0ull;
#pragma unroll
            for (int d = 0; d < 16; d++) {
                ulonglong2 wq = wq4[d * 8 + h];
                ulonglong2 wv = wv4[d * 8 + h];
                qa0 = f2fma(y2[d], wq.x, qa0);
                qa1 = f2fma(y2[d], wq.y, qa1);
                va0 = f2fma(y2[d], wv.x, va0);
                va1 = f2fma(y2[d], wv.y, va1);
            }
            float q0, q1, q2, q3, v0, v1, v2, v3;
            f2unpack(qa0, q0, q1); f2unpack(qa1, q2, q3);
            f2unpack(va0, v0, v1); f2unpack(va1, v2, v3);
            float u0 = v0 * sgk[h * 4 + 0] + v1 * sgk[h * 4 + 1];
            float u1 = v2 * sgk[h * 4 + 2] + v3 * sgk[h * 4 + 3];
            float r0 = q0 + sbr[0] + u0 * sWr[0] + u1 * sWr[4];
            float r1 = q1 + sbr[1] + u0 * sWr[1] + u1 * sWr[5];
            float r2 = q2 + sbr[2] + u0 * sWr[2] + u1 * sWr[6];
            float r3 = q3 + sbr[3] + u0 * sWr[3] + u1 * sWr[7];
            unsigned long long r0p = f2pack(r0, r0), r1p = f2pack(r1, r1);
            unsigned long long r2p = f2pack(r2, r2), r3p = f2pack(r3, r3);
#pragma unroll
            for (int e = 0; e < 8; e++) {
                oacc[e] = f2fma(r0p, wo2[(h * 4 + 0) * 8 + e], oacc[e]);
                oacc[e] = f2fma(r1p, wo2[(h * 4 + 1) * 8 + e], oacc[e]);
                oacc[e] = f2fma(r2p, wo2[(h * 4 + 2) * 8 + e], oacc[e]);
                oacc[e] = f2fma(r3p, wo2[(h * 4 + 3) * 8 + e], oacc[e]);
            }
        }
#pragma unroll
        for (int e = 0; e < 8; e++) {
            float lo, hi; f2unpack(oacc[e], lo, hi);
            xv[2 * e] += lo; xv[2 * e + 1] += hi;
        }

        // FFN
        ln_pack16(xv, sg2, sb2, y2);
        unsigned long long fout[8];
#pragma unroll
        for (int e = 0; e < 8; e++) fout[e] = f2pack(sbf2[2 * e], sbf2[2 * e + 1]);
        const unsigned long long* w1p = (const unsigned long long*)sW1;
        const unsigned long long* w2p = (const unsigned long long*)sW2;
#pragma unroll
        for (int half = 0; half < 2; half++) {
            unsigned long long ha[16];
#pragma unroll
            for (int j = 0; j < 16; j++)
                ha[j] = f2pack(sbf1[half * 32 + 2 * j], sbf1[half * 32 + 2 * j + 1]);
#pragma unroll
            for (int d = 0; d < 16; d++) {
#pragma unroll
                for (int j = 0; j < 16; j++)
                    ha[j] = f2fma(y2[d], w1p[d * 32 + half * 16 + j], ha[j]);
            }
#pragma unroll
            for (int j = 0; j < 16; j++) {
                float z0, z1; f2unpack(ha[j], z0, z1);
                float gg0 = z0 * normcdff(z0);
                float gg1 = z1 * normcdff(z1);
                int j0 = half * 32 + 2 * j;
                unsigned long long g0p = f2pack(gg0, gg0), g1p = f2pack(gg1, gg1);
#pragma unroll
                for (int e = 0; e < 8; e++) {
                    fout[e] = f2fma(g0p, w2p[j0 * 8 + e], fout[e]);
                    fout[e] = f2fma(g1p, w2p[(j0 + 1) * 8 + e], fout[e]);
                }
            }
        }
#pragma unroll
        for (int e = 0; e < 8; e++) {
            float lo, hi; f2unpack(fout[e], lo, hi);
            xv[2 * e] += lo; xv[2 * e + 1] += hi;
        }

        if (DO_Q) {
            // store new x
            float4* xo = (float4*)xp;
#pragma unroll
            for (int i = 0; i < 4; i++)
                xo[i] = make_float4(xv[4 * i], xv[4 * i + 1], xv[4 * i + 2], xv[4 * i + 3]);

            // next-layer q partials
            ln_pack16(xv, sgn, sbn, y2);
            float4 cv = g_cos[n], sv = g_sin[n];
            const ulonglong2* wqn4 = (const ulonglong2*)sWqn;
#pragma unroll
            for (int h = 0; h < 8; h++) {
                unsigned long long p0 = 0ull, p1 = 0ull;
#pragma unroll
                for (int d = 0; d < 16; d++) {
                    ulonglong2 w = wqn4[d * 8 + h];
                    p0 = f2fma(y2[d], w.x, p0);
                    p1 = f2fma(y2[d], w.y, p1);
                }
                float t0, t1, t2, t3;
                f2unpack(p0, t0, t1); f2unpack(p1, t2, t3);
                float lg = (t0 * swln[0] + t1 * swln[1] + t2 * swln[2] + t3 * swln[3]) * ATT_SCALE;
                float e = __expf(lg);
                float a0 = t0 * cv.x - t1 * sv.x;
                float a1 = t1 * cv.y + t0 * sv.y;
                float a2 = t2 * cv.z - t3 * sv.z;
                float a3 = t3 * cv.w + t2 * sv.w;
                s[h] += e;
                v[h][0] += e * a0; v[h][1] += e * a1; v[h][2] += e * a2; v[h][3] += e * a3;
            }
        } else {
            // last layer: write final projection directly; skip x store
            float acc = bout[0];
#pragma unroll
            for (int d = 0; d < 16; d++) acc += xv[d] * sWout[d];
            out[(size_t)b * NTOK + n] = acc;
        }
    }

    if (DO_Q)
        reduce_and_combine<TPB_C / 32, QSTRIDE>(s, v, g_qpart, g_cntQ, g_gq, b);
}

// ---------------- host launcher ----------------
extern "C" void kernel_launch(void* const* d_in, const int* in_sizes, int n_in,
                              void* d_out, int out_size) {
    const float* corr  = (const float*)d_in[0];
    const float* W_emb = (const float*)d_in[1];
    const float* b_emb = (const float*)d_in[2];
    const float* ln1g  = (const float*)d_in[3];
    const float* ln1b  = (const float*)d_in[4];
    const float* Wqkv  = (const float*)d_in[5];
    const float* wqlog = (const float*)d_in[6];
    const float* wklog = (const float*)d_in[7];
    const float* Wr    = (const float*)d_in[8];
    const float* br    = (const float*)d_in[9];
    const float* Wo    = (const float*)d_in[10];
    const float* bo    = (const float*)d_in[11];
    const float* ln2g  = (const float*)d_in[12];
    const float* ln2b  = (const float*)d_in[13];
    const float* Wf1   = (const float*)d_in[14];
    const float* bf1   = (const float*)d_in[15];
    const float* Wf2   = (const float*)d_in[16];
    const float* bf2   = (const float*)d_in[17];
    const float* Wout  = (const float*)d_in[18];
    const float* bout  = (const float*)d_in[19];
    float* out = (float*)d_out;

    dim3 gE(NBLK_E, BSZ);
    dim3 gB(NBLK_B, BSZ);
    dim3 gC(NBLK_C, BSZ);

    k_rotary<<<(NTOK + 255) / 256, 256>>>();
    k_embed<<<gE, TPB_E>>>(corr, W_emb, b_emb, ln1g, ln1b, Wqkv, wqlog);

    for (int i = 0; i < NLAYER; i++) {
        const float* lg1 = ln1g + i * 16;
        const float* lb1 = ln1b + i * 16;
        const float* Wl  = Wqkv + (size_t)i * 1536;
        k_passB<<<gB, TPB_B>>>(lg1, lb1, Wl, wklog + i * 2);
        if (i + 1 < NLAYER) {
            k_passC<true><<<gC, TPB_C>>>(lg1, lb1, Wl,
                                         Wr + i * 8, br + i * 4,
                                         Wo + (size_t)i * 512, bo + i * 16,
                                         ln2g + i * 16, ln2b + i * 16,
                                         Wf1 + (size_t)i * 1024, bf1 + i * 64,
                                         Wf2 + (size_t)i * 1024, bf2 + i * 16,
                                         ln1g + (i + 1) * 16, ln1b + (i + 1) * 16,
                                         Wqkv + (size_t)(i + 1) * 1536, wqlog + (i + 1) * 4,
                                         nullptr, nullptr, nullptr);
        } else {
            k_passC<false><<<gC, TPB_C>>>(lg1, lb1, Wl,
                                          Wr + i * 8, br + i * 4,
                                          Wo + (size_t)i * 512, bo + i * 16,
                                          ln2g + i * 16, ln2b + i * 16,
                                          Wf1 + (size_t)i * 1024, bf1 + i * 64,
                                          Wf2 + (size_t)i * 1024, bf2 + i * 16,
                                          nullptr, nullptr, nullptr, nullptr,
                                          Wout, bout, out);
        }
    }
}

// round 15
// speedup vs baseline: 1.0026x; 1.0026x over previous
#include <cuda_runtime.h>
#include <math.h>

// ---------------- problem constants ----------------
#define BSZ    16
#define BOTC   26
#define NTOK   50625          // 15^4
#define NLAYER 6
#define LN_EPS 1e-5f
#define ATT_SCALE 0.5f        // DH^-0.5

#define TPB_B  256
#define TPT_B  4
#define NBLK_B 50             // ceil(50625 / (256*4))
#define TPB_C  128
#define NBLK_C ((NTOK + TPB_C - 1) / TPB_C)   // 396
#define TPB_E  256
#define NBLK_E ((NTOK + TPB_E - 1) / TPB_E)   // 198
#define QSTRIDE NBLK_C        // >= NBLK_E

// ---------------- device scratch (static, allowed) ----------------
__device__ float  g_x[(size_t)BSZ * NTOK * 16];          // activations (~52MB, L2-resident)
__device__ float4 g_cos[NTOK];
__device__ float4 g_sin[NTOK];
__device__ float  g_qpart[(size_t)BSZ * 40 * QSTRIDE];   // [b][slot=h*5+c][blk]
__device__ float  g_kpart[(size_t)BSZ * 40 * NBLK_B];
__device__ float  g_gq[BSZ * 32];
__device__ float  g_gk[BSZ * 32];
__device__ unsigned g_cntQ[BSZ];
__device__ unsigned g_cntK[BSZ];

// ---------------- f32x2 packed-FMA helpers ----------------
static __device__ __forceinline__ unsigned long long f2pack(float lo, float hi) {
    unsigned long long r;
    asm("mov.b64 %0, {%1, %2};" : "=l"(r) : "f"(lo), "f"(hi));
    return r;
}
static __device__ __forceinline__ void f2unpack(unsigned long long v, float& lo, float& hi) {
    asm("mov.b64 {%0, %1}, %2;" : "=f"(lo), "=f"(hi) : "l"(v));
}
static __device__ __forceinline__ unsigned long long f2fma(unsigned long long a,
                                                           unsigned long long b,
                                                           unsigned long long c) {
    unsigned long long d;
    asm("fma.rn.f32x2 %0, %1, %2, %3;" : "=l"(d) : "l"(a), "l"(b), "l"(c));
    return d;
}

static __device__ __forceinline__ float warp_sum(float v) {
#pragma unroll
    for (int off = 16; off > 0; off >>= 1)
        v += __shfl_down_sync(0xffffffffu, v, off);
    return v;
}

// layernorm over 16, emit packed (y_d, y_d) per dim
static __device__ __forceinline__ void ln_pack16(const float* xv, const float* g, const float* b,
                                                 unsigned long long* y2) {
    float mu = 0.f;
#pragma unroll
    for (int d = 0; d < 16; d++) mu += xv[d];
    mu *= (1.f / 16.f);
    float var = 0.f;
#pragma unroll
    for (int d = 0; d < 16; d++) { float t = xv[d] - mu; var += t * t; }
    var *= (1.f / 16.f);
    float r = rsqrtf(var + LN_EPS);
#pragma unroll
    for (int d = 0; d < 16; d++) {
        float y = (xv[d] - mu) * r * g[d] + b[d];
        y2[d] = f2pack(y, y);
    }
}

// block-reduce (s,v) partials -> global partial slot; last block per batch
// combines all partials and writes normalized 32-vector to gout.
template <int NW, int STRIDE>
static __device__ __forceinline__ void reduce_and_combine(
    float s[8], float v[8][4],
    float* __restrict__ gpart, unsigned* __restrict__ cnt,
    float* __restrict__ gout, int b)
{
    __shared__ float sred[NW][40];
    __shared__ float sfin[40];
    __shared__ int lastFlag;
    const int tid = threadIdx.x, lane = tid & 31, warp = tid >> 5;

#pragma unroll
    for (int h = 0; h < 8; h++) {
        s[h] = warp_sum(s[h]);
#pragma unroll
        for (int j = 0; j < 4; j++) v[h][j] = warp_sum(v[h][j]);
    }
    if (lane == 0) {
#pragma unroll
        for (int h = 0; h < 8; h++) {
            sred[warp][h * 5 + 0] = s[h];
            sred[warp][h * 5 + 1] = v[h][0];
            sred[warp][h * 5 + 2] = v[h][1];
            sred[warp][h * 5 + 3] = v[h][2];
            sred[warp][h * 5 + 4] = v[h][3];
        }
    }
    __syncthreads();
    if (tid < 40) {
        float a = 0.f;
#pragma unroll
        for (int w = 0; w < NW; w++) a += sred[w][tid];
        gpart[((size_t)b * 40 + tid) * STRIDE + blockIdx.x] = a;
        __threadfence();
    }
    __syncthreads();
    if (tid == 0)
        lastFlag = (atomicInc(&cnt[b], gridDim.x - 1) == gridDim.x - 1);
    __syncthreads();
    if (lastFlag) {
        const int nblk = gridDim.x;
        for (int slot = warp; slot < 40; slot += NW) {
            const float* p = gpart + ((size_t)b * 40 + slot) * STRIDE;
            float a = 0.f;
            for (int i = lane; i < nblk; i += 32) a += p[i];
            a = warp_sum(a);
            if (lane == 0) sfin[slot] = a;
        }
        __syncthreads();
        if (tid < 32) {
            int h = tid >> 2, j = tid & 3;
            gout[b * 32 + tid] = sfin[h * 5 + 1 + j] / sfin[h * 5];
        }
    }
}

// ---------------- rotary tables ----------------
__global__ void k_rotary() {
    int n = blockIdx.x * blockDim.x + threadIdx.x;
    if (n >= NTOK) return;
    float fn = (float)n;
    float a0 = fn * 3.14159265358979323846f;   // fp32(pi), matches reference rounding
    float a1 = fn * 15.70796326794896619231f;  // fp32(5*pi)
    float s0, c0, s1, c1;
    sincosf(a0, &s0, &c0);
    sincosf(a1, &s1, &c1);
    g_cos[n] = make_float4(c0, c0, c1, c1);
    g_sin[n] = make_float4(s0, s0, s1, s1);
}

// ---------------- embedding + layer-0 q-softmax partials ----------------
__global__ void __launch_bounds__(TPB_E) k_embed(const float* __restrict__ corr,
                                                 const float* __restrict__ W_emb,
                                                 const float* __restrict__ b_emb,
                                                 const float* __restrict__ lng,
                                                 const float* __restrict__ lnb,
                                                 const float* __restrict__ Wqkv,
                                                 const float* __restrict__ wql) {
    __shared__ __align__(16) float sW[BOTC * 16];
    __shared__ __align__(16) float sWq[512];
    __shared__ float sb[16], sg[16], sb1[16], swl[4];
    const int tid = threadIdx.x;
    const int b = blockIdx.y;
    for (int t = tid; t < BOTC * 16; t += TPB_E) sW[t] = W_emb[t];
    for (int t = tid; t < 512; t += TPB_E) sWq[t] = Wqkv[(t >> 5) * 96 + (t & 31)];
    if (tid < 16) { sb[tid] = b_emb[tid]; sg[tid] = lng[tid]; sb1[tid] = lnb[tid]; }
    if (tid < 4) swl[tid] = wql[tid];
    __syncthreads();

    float s[8], v[8][4];
#pragma unroll
    for (int h = 0; h < 8; h++) { s[h] = 0.f; v[h][0] = v[h][1] = v[h][2] = v[h][3] = 0.f; }

    int n = blockIdx.x * TPB_E + tid;
    if (n < NTOK) {
        const unsigned long long* w2 = (const unsigned long long*)sW;
        unsigned long long acc[8];
#pragma unroll
        for (int e = 0; e < 8; e++) acc[e] = f2pack(sb[2 * e], sb[2 * e + 1]);
        const float* cp = corr + (size_t)b * BOTC * NTOK + n;
#pragma unroll
        for (int c = 0; c < BOTC; c++) {
            float rc = fmaxf(cp[(size_t)c * NTOK], 0.f);
            unsigned long long r2 = f2pack(rc, rc);
#pragma unroll
            for (int e = 0; e < 8; e++) acc[e] = f2fma(r2, w2[c * 8 + e], acc[e]);
        }
        float xv[16];
        float* xp = g_x + ((size_t)b * NTOK + n) * 16;
#pragma unroll
        for (int e = 0; e < 8; e++) {
            float lo, hi; f2unpack(acc[e], lo, hi);
            xv[2 * e] = lo; xv[2 * e + 1] = hi;
            *(float2*)(xp + 2 * e) = make_float2(lo, hi);
        }
        // layer-0 q partials
        unsigned long long y2[16];
        ln_pack16(xv, sg, sb1, y2);
        float4 cv = g_cos[n], sv = g_sin[n];
        const ulonglong2* wq4 = (const ulonglong2*)sWq;
#pragma unroll
        for (int h = 0; h < 8; h++) {
            unsigned long long p0 = 0ull, p1 = 0ull;
#pragma unroll
            for (int d = 0; d < 16; d++) {
                ulonglong2 w = wq4[d * 8 + h];
                p0 = f2fma(y2[d], w.x, p0);
                p1 = f2fma(y2[d], w.y, p1);
            }
            float t0, t1, t2, t3;
            f2unpack(p0, t0, t1); f2unpack(p1, t2, t3);
            float lg = (t0 * swl[0] + t1 * swl[1] + t2 * swl[2] + t3 * swl[3]) * ATT_SCALE;
            float e = __expf(lg);
            float a0 = t0 * cv.x - t1 * sv.x;
            float a1 = t1 * cv.y + t0 * sv.y;
            float a2 = t2 * cv.z - t3 * sv.z;
            float a3 = t3 * cv.w + t2 * sv.w;
            s[h] += e;
            v[h][0] += e * a0; v[h][1] += e * a1; v[h][2] += e * a2; v[h][3] += e * a3;
        }
    }
    reduce_and_combine<TPB_E / 32, QSTRIDE>(s, v, g_qpart, g_cntQ, g_gq, b);
}

// ---------------- pass B: k-softmax sweep (+ fused g_gk combine) ----------------
__global__ void __launch_bounds__(TPB_B) k_passB(const float* __restrict__ lng,
                                                 const float* __restrict__ lnb,
                                                 const float* __restrict__ Wqkv,
                                                 const float* __restrict__ wkl) {
    __shared__ __align__(16) float sW[512];
    __shared__ float sg[16], sb[16], swl[2], sgq[32];
    const int tid = threadIdx.x;
    const int b = blockIdx.y;
    for (int t = tid; t < 512; t += TPB_B) sW[t] = Wqkv[(t >> 5) * 96 + 32 + (t & 31)];
    if (tid < 16) { sg[tid] = lng[tid]; sb[tid] = lnb[tid]; }
    if (tid < 2)  swl[tid] = wkl[tid];
    if (tid < 32) sgq[tid] = g_gq[b * 32 + tid];
    __syncthreads();

    float s[8], v[8][4];
#pragma unroll
    for (int h = 0; h < 8; h++) { s[h] = 0.f; v[h][0] = v[h][1] = v[h][2] = v[h][3] = 0.f; }

    const ulonglong2* w4 = (const ulonglong2*)sW;

#pragma unroll
    for (int t = 0; t < TPT_B; t++) {
        int n = blockIdx.x * (TPB_B * TPT_B) + t * TPB_B + tid;
        if (n < NTOK) {
            const float* xp = g_x + ((size_t)b * NTOK + n) * 16;
            float xv[16];
#pragma unroll
            for (int i = 0; i < 4; i++) {
                float4 xl = ((const float4*)xp)[i];
                xv[4 * i] = xl.x; xv[4 * i + 1] = xl.y; xv[4 * i + 2] = xl.z; xv[4 * i + 3] = xl.w;
            }
            unsigned long long y2[16];
            ln_pack16(xv, sg, sb, y2);
            float4 cv = g_cos[n], sv = g_sin[n];
#pragma unroll
            for (int h = 0; h < 8; h++) {
                unsigned long long p0 = 0ull, p1 = 0ull;
#pragma unroll
                for (int d = 0; d < 16; d++) {
                    ulonglong2 w = w4[d * 8 + h];
                    p0 = f2fma(y2[d], w.x, p0);
                    p1 = f2fma(y2[d], w.y, p1);
                }
                float t0, t1, t2, t3;
                f2unpack(p0, t0, t1); f2unpack(p1, t2, t3);
                float k20 = t0 * sgq[h * 4 + 0] + t1 * sgq[h * 4 + 1];
                float k21 = t2 * sgq[h * 4 + 2] + t3 * sgq[h * 4 + 3];
                float lg = (k20 * swl[0] + k21 * swl[1]) * ATT_SCALE;
                float e = __expf(lg);
                float a0 = t0 * cv.x - t1 * sv.x;
                float a1 = t1 * cv.y + t0 * sv.y;
                float a2 = t2 * cv.z - t3 * sv.z;
                float a3 = t3 * cv.w + t2 * sv.w;
                s[h] += e;
                v[h][0] += e * a0; v[h][1] += e * a1; v[h][2] += e * a2; v[h][3] += e * a3;
            }
        }
    }
    reduce_and_combine<TPB_B / 32, NBLK_B>(s, v, g_kpart, g_cntK, g_gk, b);
}

// ---------------- pass C: attention out + FFN; fused next-layer q partials or final out ----------------
template <bool DO_Q>
__global__ void __launch_bounds__(TPB_C) k_passC(
    const float* __restrict__ lng1, const float* __restrict__ lnb1,
    const float* __restrict__ Wqkv,
    const float* __restrict__ Wr, const float* __restrict__ br,
    const float* __restrict__ Wo, const float* __restrict__ bo,
    const float* __restrict__ lng2, const float* __restrict__ lnb2,
    const float* __restrict__ Wf1, const float* __restrict__ bf1,
    const float* __restrict__ Wf2, const float* __restrict__ bf2,
    const float* __restrict__ lng1n, const float* __restrict__ lnb1n,
    const float* __restrict__ Wqkvn, const float* __restrict__ wqln,
    const float* __restrict__ Wout, const float* __restrict__ bout,
    float* __restrict__ out)
{
    __shared__ __align__(16) float sWq[512];
    __shared__ __align__(16) float sWv[512];
    __shared__ __align__(16) float sWo[512];
    __shared__ __align__(16) float sW1[1024];
    __shared__ __align__(16) float sW2[1024];
    __shared__ __align__(16) float sWqn[512];
    __shared__ float sg1[16], sb1[16], sg2[16], sb2[16], sgn[16], sbn[16];
    __shared__ float sWr[8], sbr[4], sbo[16], sbf1[64], sbf2[16], sgk[32], swln[4], sWout[16];
    const int tid = threadIdx.x;
    const int b = blockIdx.y;
    for (int t = tid; t < 512; t += TPB_C) {
        sWq[t] = Wqkv[(t >> 5) * 96 + (t & 31)];
        sWv[t] = Wqkv[(t >> 5) * 96 + 64 + (t & 31)];
        sWo[t] = Wo[t];
        if (DO_Q) sWqn[t] = Wqkvn[(t >> 5) * 96 + (t & 31)];
    }
    for (int t = tid; t < 1024; t += TPB_C) { sW1[t] = Wf1[t]; sW2[t] = Wf2[t]; }
    if (tid < 16) {
        sg1[tid] = lng1[tid]; sb1[tid] = lnb1[tid];
        sg2[tid] = lng2[tid]; sb2[tid] = lnb2[tid];
        sbo[tid] = bo[tid];   sbf2[tid] = bf2[tid];
        if (DO_Q) { sgn[tid] = lng1n[tid]; sbn[tid] = lnb1n[tid]; }
        else      { sWout[tid] = Wout[tid]; }
    }
    if (tid < 8) sWr[tid] = Wr[tid];
    if (tid < 4) { sbr[tid] = br[tid]; if (DO_Q) swln[tid] = wqln[tid]; }
    if (tid < 64) sbf1[tid] = bf1[tid];
    if (tid < 32) sgk[tid] = g_gk[b * 32 + tid];
    __syncthreads();

    const int n = blockIdx.x * TPB_C + tid;
    const bool act = (n < NTOK);

    float s[8], v[8][4];
    if (DO_Q) {
#pragma unroll
        for (int h = 0; h < 8; h++) { s[h] = 0.f; v[h][0] = v[h][1] = v[h][2] = v[h][3] = 0.f; }
    }

    if (act) {
        float* xp = g_x + ((size_t)b * NTOK + n) * 16;
        float xv[16];
#pragma unroll
        for (int i = 0; i < 4; i++) {
            float4 xl = ((const float4*)xp)[i];
            xv[4 * i] = xl.x; xv[4 * i + 1] = xl.y; xv[4 * i + 2] = xl.z; xv[4 * i + 3] = xl.w;
        }

        unsigned long long y2[16];
        ln_pack16(xv, sg1, sb1, y2);

        unsigned long long oacc[8];
#pragma unroll
        for (int e = 0; e < 8; e++) oacc[e] = f2pack(sbo[2 * e], sbo[2 * e + 1]);

        const ulonglong2* wq4 = (const ulonglong2*)sWq;
        const ulonglong2* wv4 = (const ulonglong2*)sWv;
        const unsigned long long* wo2 = (const unsigned long long*)sWo;

#pragma unroll
        for (int h = 0; h < 8; h++) {
            unsigned long long qa0 = 0ull, qa1 = 0ull, va0 = 0ull, va1 = 0ull;
#pragma unroll
            for (int d = 0; d < 16; d++) {
                ulonglong2 wq = wq4[d * 8 + h];
                ulonglong2 wv = wv4[d * 8 + h];
                qa0 = f2fma(y2[d], wq.x, qa0);
                qa1 = f2fma(y2[d], wq.y, qa1);
                va0 = f2fma(y2[d], wv.x, va0);
                va1 = f2fma(y2[d], wv.y, va1);
            }
            float q0, q1, q2, q3, v0, v1, v2, v3;
            f2unpack(qa0, q0, q1); f2unpack(qa1, q2, q3);
            f2unpack(va0, v0, v1); f2unpack(va1, v2, v3);
            float u0 = v0 * sgk[h * 4 + 0] + v1 * sgk[h * 4 + 1];
            float u1 = v2 * sgk[h * 4 + 2] + v3 * sgk[h * 4 + 3];
            float r0 = q0 + sbr[0] + u0 * sWr[0] + u1 * sWr[4];
            float r1 = q1 + sbr[1] + u0 * sWr[1] + u1 * sWr[5];
            float r2 = q2 + sbr[2] + u0 * sWr[2] + u1 * sWr[6];
            float r3 = q3 + sbr[3] + u0 * sWr[3] + u1 * sWr[7];
            unsigned long long r0p = f2pack(r0, r0), r1p = f2pack(r1, r1);
            unsigned long long r2p = f2pack(r2, r2), r3p = f2pack(r3, r3);
#pragma unroll
            for (int e = 0; e < 8; e++) {
                oacc[e] = f2fma(r0p, wo2[(h * 4 + 0) * 8 + e], oacc[e]);
                oacc[e] = f2fma(r1p, wo2[(h * 4 + 1) * 8 + e], oacc[e]);
                oacc[e] = f2fma(r2p, wo2[(h * 4 + 2) * 8 + e], oacc[e]);
                oacc[e] = f2fma(r3p, wo2[(h * 4 + 3) * 8 + e], oacc[e]);
            }
        }
#pragma unroll
        for (int e = 0; e < 8; e++) {
            float lo, hi; f2unpack(oacc[e], lo, hi);
            xv[2 * e] += lo; xv[2 * e + 1] += hi;
        }

        // FFN
        ln_pack16(xv, sg2, sb2, y2);
        unsigned long long fout[8];
#pragma unroll
        for (int e = 0; e < 8; e++) fout[e] = f2pack(sbf2[2 * e], sbf2[2 * e + 1]);
        const unsigned long long* w1p = (const unsigned long long*)sW1;
        const unsigned long long* w2p = (const unsigned long long*)sW2;
#pragma unroll
        for (int half = 0; half < 2; half++) {
            unsigned long long ha[16];
#pragma unroll
            for (int j = 0; j < 16; j++)
                ha[j] = f2pack(sbf1[half * 32 + 2 * j], sbf1[half * 32 + 2 * j + 1]);
#pragma unroll
            for (int d = 0; d < 16; d++) {
#pragma unroll
                for (int j = 0; j < 16; j++)
                    ha[j] = f2fma(y2[d], w1p[d * 32 + half * 16 + j], ha[j]);
            }
#pragma unroll
            for (int j = 0; j < 16; j++) {
                float z0, z1; f2unpack(ha[j], z0, z1);
                float gg0 = z0 * normcdff(z0);
                float gg1 = z1 * normcdff(z1);
                int j0 = half * 32 + 2 * j;
                unsigned long long g0p = f2pack(gg0, gg0), g1p = f2pack(gg1, gg1);
#pragma unroll
                for (int e = 0; e < 8; e++) {
                    fout[e] = f2fma(g0p, w2p[j0 * 8 + e], fout[e]);
                    fout[e] = f2fma(g1p, w2p[(j0 + 1) * 8 + e], fout[e]);
                }
            }
        }
#pragma unroll
        for (int e = 0; e < 8; e++) {
            float lo, hi; f2unpack(fout[e], lo, hi);
            xv[2 * e] += lo; xv[2 * e + 1] += hi;
        }

        if (DO_Q) {
            // store new x
            float4* xo = (float4*)xp;
#pragma unroll
            for (int i = 0; i < 4; i++)
                xo[i] = make_float4(xv[4 * i], xv[4 * i + 1], xv[4 * i + 2], xv[4 * i + 3]);

            // next-layer q partials
            ln_pack16(xv, sgn, sbn, y2);
            float4 cv = g_cos[n], sv = g_sin[n];
            const ulonglong2* wqn4 = (const ulonglong2*)sWqn;
#pragma unroll
            for (int h = 0; h < 8; h++) {
                unsigned long long p0 = 0ull, p1 = 0ull;
#pragma unroll
                for (int d = 0; d < 16; d++) {
                    ulonglong2 w = wqn4[d * 8 + h];
                    p0 = f2fma(y2[d], w.x, p0);
                    p1 = f2fma(y2[d], w.y, p1);
                }
                float t0, t1, t2, t3;
                f2unpack(p0, t0, t1); f2unpack(p1, t2, t3);
                float lg = (t0 * swln[0] + t1 * swln[1] + t2 * swln[2] + t3 * swln[3]) * ATT_SCALE;
                float e = __expf(lg);
                float a0 = t0 * cv.x - t1 * sv.x;
                float a1 = t1 * cv.y + t0 * sv.y;
                float a2 = t2 * cv.z - t3 * sv.z;
                float a3 = t3 * cv.w + t2 * sv.w;
                s[h] += e;
                v[h][0] += e * a0; v[h][1] += e * a1; v[h][2] += e * a2; v[h][3] += e * a3;
            }
        } else {
            // last layer: write final projection directly; skip x store
            float acc = bout[0];
#pragma unroll
            for (int d = 0; d < 16; d++) acc += xv[d] * sWout[d];
            out[(size_t)b * NTOK + n] = acc;
        }
    }

    if (DO_Q)
        reduce_and_combine<TPB_C / 32, QSTRIDE>(s, v, g_qpart, g_cntQ, g_gq, b);
}

// ---------------- host launcher ----------------
extern "C" void kernel_launch(void* const* d_in, const int* in_sizes, int n_in,
                              void* d_out, int out_size) {
    const float* corr  = (const float*)d_in[0];
    const float* W_emb = (const float*)d_in[1];
    const float* b_emb = (const float*)d_in[2];
    const float* ln1g  = (const float*)d_in[3];
    const float* ln1b  = (const float*)d_in[4];
    const float* Wqkv  = (const float*)d_in[5];
    const float* wqlog = (const float*)d_in[6];
    const float* wklog = (const float*)d_in[7];
    const float* Wr    = (const float*)d_in[8];
    const float* br    = (const float*)d_in[9];
    const float* Wo    = (const float*)d_in[10];
    const float* bo    = (const float*)d_in[11];
    const float* ln2g  = (const float*)d_in[12];
    const float* ln2b  = (const float*)d_in[13];
    const float* Wf1   = (const float*)d_in[14];
    const float* bf1   = (const float*)d_in[15];
    const float* Wf2   = (const float*)d_in[16];
    const float* bf2   = (const float*)d_in[17];
    const float* Wout  = (const float*)d_in[18];
    const float* bout  = (const float*)d_in[19];
    float* out = (float*)d_out;

    dim3 gE(NBLK_E, BSZ);
    dim3 gB(NBLK_B, BSZ);
    dim3 gC(NBLK_C, BSZ);

    k_rotary<<<(NTOK + 255) / 256, 256>>>();
    k_embed<<<gE, TPB_E>>>(corr, W_emb, b_emb, ln1g, ln1b, Wqkv, wqlog);

    for (int i = 0; i < NLAYER; i++) {
        const float* lg1 = ln1g + i * 16;
        const float* lb1 = ln1b + i * 16;
        const float* Wl  = Wqkv + (size_t)i * 1536;
        k_passB<<<gB, TPB_B>>>(lg1, lb1, Wl, wklog + i * 2);
        if (i + 1 < NLAYER) {
            k_passC<true><<<gC, TPB_C>>>(lg1, lb1, Wl,
                                         Wr + i * 8, br + i * 4,
                                         Wo + (size_t)i * 512, bo + i * 16,
                                         ln2g + i * 16, ln2b + i * 16,
                                         Wf1 + (size_t)i * 1024, bf1 + i * 64,
                                         Wf2 + (size_t)i * 1024, bf2 + i * 16,
                                         ln1g + (i + 1) * 16, ln1b + (i + 1) * 16,
                                         Wqkv + (size_t)(i + 1) * 1536, wqlog + (i + 1) * 4,
                                         nullptr, nullptr, nullptr);
        } else {
            k_passC<false><<<gC, TPB_C>>>(lg1, lb1, Wl,
                                          Wr + i * 8, br + i * 4,
                                          Wo + (size_t)i * 512, bo + i * 16,
                                          ln2g + i * 16, ln2b + i * 16,
                                          Wf1 + (size_t)i * 1024, bf1 + i * 64,
                                          Wf2 + (size_t)i * 1024, bf2 + i * 16,
                                          nullptr, nullptr, nullptr, nullptr,
                                          Wout, bout, out);
        }
    }
}